// round 5
// baseline (speedup 1.0000x reference)
#include <cuda_runtime.h>
#include <cuda_bf16.h>
#include <math.h>

// ---------------- problem constants ----------------------------------------
#define MAXN 100000
#define MAXE 1600000
#define H 128
#define NF 133

// ---------------- static scratch: referenced ONLY inside device code --------
__device__ float g_dinv[MAXN];
__device__ int   g_deg[MAXN];
__device__ int   g_rowptr[MAXN + 1];
__device__ int   g_cursor[MAXN];
__device__ int   g_col[MAXE];
__device__ float g_bufA[(size_t)MAXN * H];   // hs  (scaled GEMM output)
__device__ float g_bufB[(size_t)MAXN * H];   // layer activations
__device__ int   g_bsum[512];
__device__ int   g_boff[512];

// ---------------- preprocessing kernels -------------------------------------
__global__ void k_zero_deg(int n) {
    int i = blockIdx.x * blockDim.x + threadIdx.x;
    if (i < n) g_deg[i] = 0;
}

// edge_index is int32, shape (2, E): ei[0..E) = src, ei[E..2E) = dst
__global__ void k_count(const int* __restrict__ ei, int E, int n) {
    int e = blockIdx.x * blockDim.x + threadIdx.x;
    if (e < E) {
        int d = ei[E + e];
        if ((unsigned)d < (unsigned)n) atomicAdd(&g_deg[d], 1);
    }
}

// per-block partial sums of deg (block = 512)
__global__ void k_partial(int n) {
    __shared__ int s[512];
    int t = threadIdx.x;
    int i = blockIdx.x * 512 + t;
    s[t] = (i < n) ? g_deg[i] : 0;
    __syncthreads();
    for (int off = 256; off > 0; off >>= 1) {
        if (t < off) s[t] += s[t + off];
        __syncthreads();
    }
    if (t == 0) g_bsum[blockIdx.x] = s[0];
}

// single-block exclusive scan of block sums (nb <= 512); also rowptr[N]=total
__global__ void k_scanb(int nb, int n) {
    __shared__ int s[512];
    int t = threadIdx.x;
    int v = (t < nb) ? g_bsum[t] : 0;
    s[t] = v;
    __syncthreads();
    for (int off = 1; off < 512; off <<= 1) {
        int x = (t >= off) ? s[t - off] : 0;
        __syncthreads();
        s[t] += x;
        __syncthreads();
    }
    if (t < nb) g_boff[t] = s[t] - v;           // exclusive
    if (t == 511) g_rowptr[n] = s[511];         // total = E
}

// per-block exclusive scan + offset -> rowptr; also dinv and fill-cursor init
__global__ void k_rowptr(int n) {
    __shared__ int s[512];
    int t = threadIdx.x;
    int i = blockIdx.x * 512 + t;
    int v = (i < n) ? g_deg[i] : 0;
    s[t] = v;
    __syncthreads();
    for (int off = 1; off < 512; off <<= 1) {
        int x = (t >= off) ? s[t - off] : 0;
        __syncthreads();
        s[t] += x;
        __syncthreads();
    }
    if (i < n) {
        int rp = g_boff[blockIdx.x] + s[t] - v;  // exclusive prefix
        g_rowptr[i] = rp;
        g_cursor[i] = rp;
        g_dinv[i] = rsqrtf((float)v + 1.0f);
    }
}

__global__ void k_fill(const int* __restrict__ ei, int E, int n) {
    int e = blockIdx.x * blockDim.x + threadIdx.x;
    if (e < E) {
        int srcv = ei[e];
        int d    = ei[E + e];
        if ((unsigned)d < (unsigned)n && (unsigned)srcv < (unsigned)n) {
            int pos = atomicAdd(&g_cursor[d], 1);
            if ((unsigned)pos < (unsigned)E) g_col[pos] = srcv;
        }
    }
}

// ---------------- GEMM: g_bufA = (A[M,K] @ W[K,128]) * dinv[row] -------------
// A = Aext if non-null (layer-0 input x), else g_bufB (previous activations).
// 128x128x8 tile, 256 threads, 8x8 microtile per thread.
__global__ __launch_bounds__(256, 2)
void k_gemm_scale(const float* __restrict__ Aext, const float* __restrict__ W,
                  int M, int K) {
    const float* __restrict__ A = Aext ? Aext : g_bufB;
    __shared__ float As[8][128];
    __shared__ float Bs[8][128];
    const int tid = threadIdx.x;
    const int row0 = blockIdx.x * 128;
    const int tx = tid & 15;         // 16 cols of threads
    const int ty = tid >> 4;         // 16 rows of threads

    float acc[8][8];
#pragma unroll
    for (int i = 0; i < 8; i++)
#pragma unroll
        for (int j = 0; j < 8; j++) acc[i][j] = 0.0f;

    for (int k0 = 0; k0 < K; k0 += 8) {
        // load A tile (128 rows x 8 k), transposed into As[k][row]
#pragma unroll
        for (int l = 0; l < 4; l++) {
            int idx = tid * 4 + l;           // 0..1023
            int r = idx >> 3;                // 0..127
            int kk = idx & 7;
            int gr = row0 + r, gk = k0 + kk;
            float v = 0.0f;
            if (gr < M && gk < K) v = A[(size_t)gr * K + gk];
            As[kk][r] = v;
        }
        // load W tile (8 k x 128 cols), coalesced
#pragma unroll
        for (int l = 0; l < 4; l++) {
            int idx = tid + l * 256;
            int kk = idx >> 7;
            int c = idx & 127;
            int gk = k0 + kk;
            Bs[kk][c] = (gk < K) ? W[(size_t)gk * H + c] : 0.0f;
        }
        __syncthreads();
#pragma unroll
        for (int kk = 0; kk < 8; kk++) {
            float ra[8], rb[8];
#pragma unroll
            for (int i = 0; i < 8; i++) ra[i] = As[kk][ty * 8 + i];
#pragma unroll
            for (int j = 0; j < 8; j++) rb[j] = Bs[kk][tx * 8 + j];
#pragma unroll
            for (int i = 0; i < 8; i++)
#pragma unroll
                for (int j = 0; j < 8; j++) acc[i][j] += ra[i] * rb[j];
        }
        __syncthreads();
    }

    // epilogue: scale each output row by dinv[row], write to g_bufA
#pragma unroll
    for (int i = 0; i < 8; i++) {
        int r = row0 + ty * 8 + i;
        if (r < M) {
            float di = g_dinv[r];
            float* orow = g_bufA + (size_t)r * H + tx * 8;
#pragma unroll
            for (int j = 0; j < 8; j++) orow[j] = acc[i][j] * di;
        }
    }
}

// ---------------- aggregation: warp per node --------------------------------
// out_i = tanh(dinv_i * (hs_i + sum_{e in row i} hs[col[e]]) + b)
// hs = g_bufA; out = outext if non-null (final layer -> d_out), else g_bufB.
__global__ __launch_bounds__(256)
void k_aggregate(const float* __restrict__ bias, float* outext, int n) {
    const float* __restrict__ hs = g_bufA;
    float* __restrict__ out = outext ? outext : g_bufB;

    int warp = (blockIdx.x * blockDim.x + threadIdx.x) >> 5;
    if (warp >= n) return;
    int lane = threadIdx.x & 31;

    const float4* row_i = (const float4*)(hs + (size_t)warp * H);
    float4 acc = row_i[lane];                 // self term (hs_i)

    int e = g_rowptr[warp];
    int end = g_rowptr[warp + 1];
    // unroll-2 for MLP
    for (; e + 1 < end; e += 2) {
        int j0 = g_col[e];
        int j1 = g_col[e + 1];
        float4 v0 = ((const float4*)(hs + (size_t)j0 * H))[lane];
        float4 v1 = ((const float4*)(hs + (size_t)j1 * H))[lane];
        acc.x += v0.x; acc.y += v0.y; acc.z += v0.z; acc.w += v0.w;
        acc.x += v1.x; acc.y += v1.y; acc.z += v1.z; acc.w += v1.w;
    }
    if (e < end) {
        int j0 = g_col[e];
        float4 v0 = ((const float4*)(hs + (size_t)j0 * H))[lane];
        acc.x += v0.x; acc.y += v0.y; acc.z += v0.z; acc.w += v0.w;
    }

    float di = g_dinv[warp];
    float4 bb = ((const float4*)bias)[lane];
    float4 o;
    o.x = tanhf(di * acc.x + bb.x);
    o.y = tanhf(di * acc.y + bb.y);
    o.z = tanhf(di * acc.z + bb.z);
    o.w = tanhf(di * acc.w + bb.w);
    ((float4*)(out + (size_t)warp * H))[lane] = o;
}

// ---------------- launch -----------------------------------------------------
extern "C" void kernel_launch(void* const* d_in, const int* in_sizes, int n_in,
                              void* d_out, int out_size) {
    const float* x  = (const float*)d_in[0];
    const int*   ei = (const int*)d_in[1];       // int32 (2, E)
    const float* W0 = (const float*)d_in[2];
    const float* b0 = (const float*)d_in[3];
    const float* W1 = (const float*)d_in[4];
    const float* b1 = (const float*)d_in[5];
    const float* W2 = (const float*)d_in[6];
    const float* b2 = (const float*)d_in[7];
    const float* W3 = (const float*)d_in[8];
    const float* b3 = (const float*)d_in[9];
    float* out = (float*)d_out;

    int N = in_sizes[0] / NF;
    int E = in_sizes[1] / 2;
    if (N > MAXN) N = MAXN;
    if (E > MAXE) E = MAXE;

    int nb = (N + 511) / 512;

    k_zero_deg<<<(N + 255) / 256, 256>>>(N);
    k_count<<<(E + 255) / 256, 256>>>(ei, E, N);
    k_partial<<<nb, 512>>>(N);
    k_scanb<<<1, 512>>>(nb, N);
    k_rowptr<<<nb, 512>>>(N);
    k_fill<<<(E + 255) / 256, 256>>>(ei, E, N);

    int gemm_grid = (N + 127) / 128;
    int agg_grid  = (N + 7) / 8;   // 8 warps per 256-thread block

    // layer 0: x [N,133] -> g_bufA (hs) -> g_bufB
    k_gemm_scale<<<gemm_grid, 256>>>(x, W0, N, NF);
    k_aggregate<<<agg_grid, 256>>>(b0, nullptr, N);
    // layer 1 (A = g_bufB internally)
    k_gemm_scale<<<gemm_grid, 256>>>(nullptr, W1, N, H);
    k_aggregate<<<agg_grid, 256>>>(b1, nullptr, N);
    // layer 2
    k_gemm_scale<<<gemm_grid, 256>>>(nullptr, W2, N, H);
    k_aggregate<<<agg_grid, 256>>>(b2, nullptr, N);
    // layer 3 -> d_out
    k_gemm_scale<<<gemm_grid, 256>>>(nullptr, W3, N, H);
    k_aggregate<<<agg_grid, 256>>>(b3, out, N);
}

// round 6
// speedup vs baseline: 2.5370x; 2.5370x over previous
#include <cuda_runtime.h>
#include <cuda_bf16.h>
#include <math.h>
#include <stdint.h>

// ---------------- problem constants ----------------------------------------
#define MAXN 100000
#define MAXE 1600000
#define H 128
#define NF 133

// ---------------- static scratch: referenced ONLY inside device code --------
__device__ float g_dinv[MAXN];
__device__ int   g_deg[MAXN];
__device__ int   g_rowptr[MAXN + 1];
__device__ int   g_cursor[MAXN];
__device__ int   g_col[MAXE];
__device__ float g_bufA[(size_t)MAXN * H];   // hs  (scaled GEMM output)
__device__ float g_bufB[(size_t)MAXN * H];   // layer activations
__device__ int   g_bsum[512];
__device__ int   g_boff[512];

// ---------------- preprocessing kernels -------------------------------------
__global__ void k_zero_deg(int n) {
    int i = blockIdx.x * blockDim.x + threadIdx.x;
    if (i < n) g_deg[i] = 0;
}

// edge_index is int32, shape (2, E): ei[0..E) = src, ei[E..2E) = dst
__global__ void k_count(const int* __restrict__ ei, int E, int n) {
    int e = blockIdx.x * blockDim.x + threadIdx.x;
    if (e < E) {
        int d = ei[E + e];
        if ((unsigned)d < (unsigned)n) atomicAdd(&g_deg[d], 1);
    }
}

__global__ void k_partial(int n) {
    __shared__ int s[512];
    int t = threadIdx.x;
    int i = blockIdx.x * 512 + t;
    s[t] = (i < n) ? g_deg[i] : 0;
    __syncthreads();
    for (int off = 256; off > 0; off >>= 1) {
        if (t < off) s[t] += s[t + off];
        __syncthreads();
    }
    if (t == 0) g_bsum[blockIdx.x] = s[0];
}

__global__ void k_scanb(int nb, int n) {
    __shared__ int s[512];
    int t = threadIdx.x;
    int v = (t < nb) ? g_bsum[t] : 0;
    s[t] = v;
    __syncthreads();
    for (int off = 1; off < 512; off <<= 1) {
        int x = (t >= off) ? s[t - off] : 0;
        __syncthreads();
        s[t] += x;
        __syncthreads();
    }
    if (t < nb) g_boff[t] = s[t] - v;           // exclusive
    if (t == 511) g_rowptr[n] = s[511];         // total = E
}

__global__ void k_rowptr(int n) {
    __shared__ int s[512];
    int t = threadIdx.x;
    int i = blockIdx.x * 512 + t;
    int v = (i < n) ? g_deg[i] : 0;
    s[t] = v;
    __syncthreads();
    for (int off = 1; off < 512; off <<= 1) {
        int x = (t >= off) ? s[t - off] : 0;
        __syncthreads();
        s[t] += x;
        __syncthreads();
    }
    if (i < n) {
        int rp = g_boff[blockIdx.x] + s[t] - v;
        g_rowptr[i] = rp;
        g_cursor[i] = rp;
        g_dinv[i] = rsqrtf((float)v + 1.0f);
    }
}

__global__ void k_fill(const int* __restrict__ ei, int E, int n) {
    int e = blockIdx.x * blockDim.x + threadIdx.x;
    if (e < E) {
        int srcv = ei[e];
        int d    = ei[E + e];
        if ((unsigned)d < (unsigned)n && (unsigned)srcv < (unsigned)n) {
            int pos = atomicAdd(&g_cursor[d], 1);
            if ((unsigned)pos < (unsigned)E) g_col[pos] = srcv;
        }
    }
}

// ---------------- tf32 helpers ----------------------------------------------
__device__ __forceinline__ uint32_t f2tf32(float x) {
    uint32_t r;
    asm("cvt.rna.tf32.f32 %0, %1;" : "=r"(r) : "f"(x));
    return r;
}

__device__ __forceinline__ void mma_tf32(float c[4], const uint32_t a[4],
                                         const uint32_t b[2]) {
    asm volatile(
        "mma.sync.aligned.m16n8k8.row.col.f32.tf32.tf32.f32 "
        "{%0,%1,%2,%3}, {%4,%5,%6,%7}, {%8,%9}, {%0,%1,%2,%3};"
        : "+f"(c[0]), "+f"(c[1]), "+f"(c[2]), "+f"(c[3])
        : "r"(a[0]), "r"(a[1]), "r"(a[2]), "r"(a[3]), "r"(b[0]), "r"(b[1]));
}

// ---------------- GEMM (tf32 tensor core) ------------------------------------
// g_bufA = (A[M,K] @ W[K,128]) * dinv[row];  A = Aext ? Aext : g_bufB.
// CTA tile 128x128, BK=16, 8 warps each computing 32x64.
#define BK 16
#define LDS_PAD 132   // 128 + 4 padding (words)

__global__ __launch_bounds__(256, 2)
void k_gemm_tf32(const float* __restrict__ Aext, const float* __restrict__ W,
                 int M, int K) {
    const float* __restrict__ A = Aext ? Aext : g_bufB;
    __shared__ uint32_t As[BK * LDS_PAD];   // As[k][m], tf32 bits
    __shared__ uint32_t Bs[BK * LDS_PAD];   // Bs[k][n], tf32 bits

    const int tid  = threadIdx.x;
    const int lane = tid & 31;
    const int w    = tid >> 5;
    const int wm   = (w >> 1) * 32;   // warp row offset in tile: 0/32/64/96
    const int wn   = (w & 1) * 64;    // warp col offset: 0/64
    const int grp  = lane >> 2;       // 0..7
    const int qid  = lane & 3;        // 0..3
    const int row0 = blockIdx.x * 128;

    float acc[2][8][4];
#pragma unroll
    for (int mi = 0; mi < 2; mi++)
#pragma unroll
        for (int ni = 0; ni < 8; ni++)
#pragma unroll
            for (int r = 0; r < 4; r++) acc[mi][ni][r] = 0.0f;

    const int npanels = (K + BK - 1) / BK;
    for (int p = 0; p < npanels; p++) {
        const int k0 = p * BK;
        // A tile: 128 rows x 16 k -> As[k][m]  (2048 elems, 8 per thread)
#pragma unroll
        for (int it = 0; it < 8; it++) {
            int idx = tid + it * 256;
            int m = idx >> 4, k = idx & 15;
            int gr = row0 + m, gk = k0 + k;
            float v = (gr < M && gk < K) ? A[(size_t)gr * K + gk] : 0.0f;
            As[k * LDS_PAD + m] = f2tf32(v);
        }
        // W tile: 16 k x 128 n -> Bs[k][n]  (coalesced)
#pragma unroll
        for (int it = 0; it < 8; it++) {
            int idx = tid + it * 256;
            int k = idx >> 7, n = idx & 127;
            int gk = k0 + k;
            float v = (gk < K) ? W[(size_t)gk * H + n] : 0.0f;
            Bs[k * LDS_PAD + n] = f2tf32(v);
        }
        __syncthreads();

#pragma unroll
        for (int ks = 0; ks < BK; ks += 8) {
            uint32_t afr[2][4];
#pragma unroll
            for (int mi = 0; mi < 2; mi++) {
                int mbase = wm + mi * 16;
                afr[mi][0] = As[(ks + qid)     * LDS_PAD + mbase + grp];
                afr[mi][1] = As[(ks + qid)     * LDS_PAD + mbase + grp + 8];
                afr[mi][2] = As[(ks + qid + 4) * LDS_PAD + mbase + grp];
                afr[mi][3] = As[(ks + qid + 4) * LDS_PAD + mbase + grp + 8];
            }
            uint32_t bfr[8][2];
#pragma unroll
            for (int ni = 0; ni < 8; ni++) {
                int nbase = wn + ni * 8;
                bfr[ni][0] = Bs[(ks + qid)     * LDS_PAD + nbase + grp];
                bfr[ni][1] = Bs[(ks + qid + 4) * LDS_PAD + nbase + grp];
            }
#pragma unroll
            for (int mi = 0; mi < 2; mi++)
#pragma unroll
                for (int ni = 0; ni < 8; ni++)
                    mma_tf32(acc[mi][ni], afr[mi], bfr[ni]);
        }
        __syncthreads();
    }

    // epilogue: D rows r0=base+grp, r1=r0+8; cols qid*2, qid*2+1 per n-frag.
#pragma unroll
    for (int mi = 0; mi < 2; mi++) {
        int r0 = row0 + wm + mi * 16 + grp;
        int r1 = r0 + 8;
        float d0 = (r0 < M) ? g_dinv[r0] : 0.0f;
        float d1 = (r1 < M) ? g_dinv[r1] : 0.0f;
#pragma unroll
        for (int ni = 0; ni < 8; ni++) {
            int c = wn + ni * 8 + qid * 2;
            if (r0 < M) {
                float2 v = make_float2(acc[mi][ni][0] * d0, acc[mi][ni][1] * d0);
                *(float2*)(g_bufA + (size_t)r0 * H + c) = v;
            }
            if (r1 < M) {
                float2 v = make_float2(acc[mi][ni][2] * d1, acc[mi][ni][3] * d1);
                *(float2*)(g_bufA + (size_t)r1 * H + c) = v;
            }
        }
    }
}

// ---------------- aggregation: warp per node --------------------------------
// out_i = tanh(dinv_i * (hs_i + sum_{e in row i} hs[col[e]]) + b)
__global__ __launch_bounds__(256)
void k_aggregate(const float* __restrict__ bias, float* outext, int n) {
    const float* __restrict__ hs = g_bufA;
    float* __restrict__ out = outext ? outext : g_bufB;

    int warp = (blockIdx.x * blockDim.x + threadIdx.x) >> 5;
    if (warp >= n) return;
    int lane = threadIdx.x & 31;

    const float4* row_i = (const float4*)(hs + (size_t)warp * H);
    float4 acc = row_i[lane];                 // self term (hs_i)

    int e = g_rowptr[warp];
    int end = g_rowptr[warp + 1];
    for (; e + 1 < end; e += 2) {
        int j0 = g_col[e];
        int j1 = g_col[e + 1];
        float4 v0 = ((const float4*)(hs + (size_t)j0 * H))[lane];
        float4 v1 = ((const float4*)(hs + (size_t)j1 * H))[lane];
        acc.x += v0.x; acc.y += v0.y; acc.z += v0.z; acc.w += v0.w;
        acc.x += v1.x; acc.y += v1.y; acc.z += v1.z; acc.w += v1.w;
    }
    if (e < end) {
        int j0 = g_col[e];
        float4 v0 = ((const float4*)(hs + (size_t)j0 * H))[lane];
        acc.x += v0.x; acc.y += v0.y; acc.z += v0.z; acc.w += v0.w;
    }

    float di = g_dinv[warp];
    float4 bb = ((const float4*)bias)[lane];
    float4 o;
    o.x = tanhf(di * acc.x + bb.x);
    o.y = tanhf(di * acc.y + bb.y);
    o.z = tanhf(di * acc.z + bb.z);
    o.w = tanhf(di * acc.w + bb.w);
    ((float4*)(out + (size_t)warp * H))[lane] = o;
}

// ---------------- launch -----------------------------------------------------
extern "C" void kernel_launch(void* const* d_in, const int* in_sizes, int n_in,
                              void* d_out, int out_size) {
    const float* x  = (const float*)d_in[0];
    const int*   ei = (const int*)d_in[1];       // int32 (2, E)
    const float* W0 = (const float*)d_in[2];
    const float* b0 = (const float*)d_in[3];
    const float* W1 = (const float*)d_in[4];
    const float* b1 = (const float*)d_in[5];
    const float* W2 = (const float*)d_in[6];
    const float* b2 = (const float*)d_in[7];
    const float* W3 = (const float*)d_in[8];
    const float* b3 = (const float*)d_in[9];
    float* out = (float*)d_out;

    int N = in_sizes[0] / NF;
    int E = in_sizes[1] / 2;
    if (N > MAXN) N = MAXN;
    if (E > MAXE) E = MAXE;

    int nb = (N + 511) / 512;

    k_zero_deg<<<(N + 255) / 256, 256>>>(N);
    k_count<<<(E + 255) / 256, 256>>>(ei, E, N);
    k_partial<<<nb, 512>>>(N);
    k_scanb<<<1, 512>>>(nb, N);
    k_rowptr<<<nb, 512>>>(N);
    k_fill<<<(E + 255) / 256, 256>>>(ei, E, N);

    int gemm_grid = (N + 127) / 128;
    int agg_grid  = (N + 7) / 8;   // 8 warps per 256-thread block

    // layer 0: x [N,133] -> g_bufA (hs) -> g_bufB
    k_gemm_tf32<<<gemm_grid, 256>>>(x, W0, N, NF);
    k_aggregate<<<agg_grid, 256>>>(b0, nullptr, N);
    // layer 1 (A = g_bufB internally)
    k_gemm_tf32<<<gemm_grid, 256>>>(nullptr, W1, N, H);
    k_aggregate<<<agg_grid, 256>>>(b1, nullptr, N);
    // layer 2
    k_gemm_tf32<<<gemm_grid, 256>>>(nullptr, W2, N, H);
    k_aggregate<<<agg_grid, 256>>>(b2, nullptr, N);
    // layer 3 -> d_out
    k_gemm_tf32<<<gemm_grid, 256>>>(nullptr, W3, N, H);
    k_aggregate<<<agg_grid, 256>>>(b3, out, N);
}

// round 10
// speedup vs baseline: 2.6316x; 1.0373x over previous
#include <cuda_runtime.h>
#include <cuda_bf16.h>
#include <math.h>
#include <stdint.h>

// ---------------- problem constants ----------------------------------------
#define MAXN 100000
#define MAXE 1600000
#define H 128
#define NF 133
#define K0P 144          // layer-0 K padded to multiple of 16

// ---------------- static scratch: referenced ONLY inside device code --------
__device__ float g_dinv[MAXN];
__device__ int   g_deg[MAXN];
__device__ int   g_rowptr[MAXN + 1];
__device__ int   g_cursor[MAXN];
__device__ int   g_col[MAXE];
__device__ float g_bufA[(size_t)MAXN * H];    // hs  (scaled GEMM output)
__device__ float g_bufB[(size_t)MAXN * H];    // activations (tf32-rounded)
__device__ float g_xr[(size_t)MAXN * K0P];    // x, tf32-rounded + padded
__device__ float g_wr0[K0P * H];              // W0 rounded + padded
__device__ float g_wr1[H * H];
__device__ float g_wr2[H * H];
__device__ float g_wr3[H * H];
__device__ int   g_bsum[512];
__device__ int   g_boff[512];

// ---------------- tf32 helpers ----------------------------------------------
__device__ __forceinline__ uint32_t f2tf32(float x) {
    uint32_t r;
    asm("cvt.rna.tf32.f32 %0, %1;" : "=r"(r) : "f"(x));
    return r;
}
__device__ __forceinline__ float rnd_tf32(float x) {
    return __uint_as_float(f2tf32(x));
}

__device__ __forceinline__ void mma_tf32(float c[4], const uint32_t a[4],
                                         const uint32_t b[2]) {
    asm volatile(
        "mma.sync.aligned.m16n8k8.row.col.f32.tf32.tf32.f32 "
        "{%0,%1,%2,%3}, {%4,%5,%6,%7}, {%8,%9}, {%0,%1,%2,%3};"
        : "+f"(c[0]), "+f"(c[1]), "+f"(c[2]), "+f"(c[3])
        : "r"(a[0]), "r"(a[1]), "r"(a[2]), "r"(a[3]), "r"(b[0]), "r"(b[1]));
}

__device__ __forceinline__ void cp16(uint32_t dst, const void* src, bool pred) {
    int sz = pred ? 16 : 0;
    asm volatile("cp.async.ca.shared.global [%0], [%1], 16, %2;"
                 :: "r"(dst), "l"(src), "r"(sz));
}
__device__ __forceinline__ void cp_commit() {
    asm volatile("cp.async.commit_group;");
}
template <int NN>
__device__ __forceinline__ void cp_wait() {
    asm volatile("cp.async.wait_group %0;" :: "n"(NN));
}

// ---------------- prep: round inputs/weights to tf32 ------------------------
__global__ void k_prep_x(const float* __restrict__ x, int n) {
    int idx = blockIdx.x * blockDim.x + threadIdx.x;
    if (idx >= n * K0P) return;
    int row = idx / K0P, col = idx - row * K0P;
    float v = (col < NF) ? rnd_tf32(x[(size_t)row * NF + col]) : 0.0f;
    g_xr[idx] = v;
}

__global__ void k_prep_w(const float* __restrict__ W0, const float* __restrict__ W1,
                         const float* __restrict__ W2, const float* __restrict__ W3) {
    int idx = blockIdx.x * blockDim.x + threadIdx.x;
    if (idx < K0P * H) {
        int k = idx >> 7;
        g_wr0[idx] = (k < NF) ? rnd_tf32(W0[idx]) : 0.0f;
    } else if (idx < K0P * H + H * H) {
        g_wr1[idx - K0P * H] = rnd_tf32(W1[idx - K0P * H]);
    } else if (idx < K0P * H + 2 * H * H) {
        g_wr2[idx - K0P * H - H * H] = rnd_tf32(W2[idx - K0P * H - H * H]);
    } else if (idx < K0P * H + 3 * H * H) {
        g_wr3[idx - K0P * H - 2 * H * H] = rnd_tf32(W3[idx - K0P * H - 2 * H * H]);
    }
}

// ---------------- preprocessing kernels -------------------------------------
__global__ void k_zero_deg(int n) {
    int i = blockIdx.x * blockDim.x + threadIdx.x;
    if (i < n) g_deg[i] = 0;
}

__global__ void k_count(const int* __restrict__ ei, int E, int n) {
    int e = blockIdx.x * blockDim.x + threadIdx.x;
    if (e < E) {
        int d = ei[E + e];
        if ((unsigned)d < (unsigned)n) atomicAdd(&g_deg[d], 1);
    }
}

__global__ void k_partial(int n) {
    __shared__ int s[512];
    int t = threadIdx.x;
    int i = blockIdx.x * 512 + t;
    s[t] = (i < n) ? g_deg[i] : 0;
    __syncthreads();
    for (int off = 256; off > 0; off >>= 1) {
        if (t < off) s[t] += s[t + off];
        __syncthreads();
    }
    if (t == 0) g_bsum[blockIdx.x] = s[0];
}

__global__ void k_scanb(int nb, int n) {
    __shared__ int s[512];
    int t = threadIdx.x;
    int v = (t < nb) ? g_bsum[t] : 0;
    s[t] = v;
    __syncthreads();
    for (int off = 1; off < 512; off <<= 1) {
        int x = (t >= off) ? s[t - off] : 0;
        __syncthreads();
        s[t] += x;
        __syncthreads();
    }
    if (t < nb) g_boff[t] = s[t] - v;
    if (t == 511) g_rowptr[n] = s[511];
}

__global__ void k_rowptr(int n) {
    __shared__ int s[512];
    int t = threadIdx.x;
    int i = blockIdx.x * 512 + t;
    int v = (i < n) ? g_deg[i] : 0;
    s[t] = v;
    __syncthreads();
    for (int off = 1; off < 512; off <<= 1) {
        int x = (t >= off) ? s[t - off] : 0;
        __syncthreads();
        s[t] += x;
        __syncthreads();
    }
    if (i < n) {
        int rp = g_boff[blockIdx.x] + s[t] - v;
        g_rowptr[i] = rp;
        g_cursor[i] = rp;
        g_dinv[i] = rsqrtf((float)v + 1.0f);
    }
}

__global__ void k_fill(const int* __restrict__ ei, int E, int n) {
    int e = blockIdx.x * blockDim.x + threadIdx.x;
    if (e < E) {
        int srcv = ei[e];
        int d    = ei[E + e];
        if ((unsigned)d < (unsigned)n && (unsigned)srcv < (unsigned)n) {
            int pos = atomicAdd(&g_cursor[d], 1);
            if ((unsigned)pos < (unsigned)E) g_col[pos] = srcv;
        }
    }
}

// ---------------- GEMM (tf32 TC, cp.async double-buffered) -------------------
// g_bufA = (A[M,K] @ Wr[K,128]) * dinv[row].
// asel: 0 -> A = g_xr (SA=K0P), 1 -> A = g_bufB (SA=H).
// wsel: 0..3 -> g_wr0..g_wr3. All selected INSIDE device code (no host symbols).
// Inputs pre-rounded to tf32, so raw fp32 bits feed the MMA exactly.
#define ASTRIDE 20     // words per A smem row (16 + 4 pad, keeps 16B align)
#define WSTRIDE 132    // words per W smem row (128 + 4 pad)

__global__ __launch_bounds__(256, 2)
void k_gemm_pipe(int asel, int wsel, int M, int K, int SA) {
    const float* __restrict__ A  = (asel == 0) ? g_xr : g_bufB;
    const float* __restrict__ Wr = (wsel == 0) ? g_wr0 :
                                   (wsel == 1) ? g_wr1 :
                                   (wsel == 2) ? g_wr2 : g_wr3;
    __shared__ float As[2][128 * ASTRIDE];
    __shared__ float Ws[2][16 * WSTRIDE];

    const int tid  = threadIdx.x;
    const int lane = tid & 31;
    const int w    = tid >> 5;
    const int wm   = (w >> 1) * 32;
    const int wn   = (w & 1) * 64;
    const int grp  = lane >> 2;
    const int qid  = lane & 3;
    const int row0 = blockIdx.x * 128;
    const int P    = K >> 4;          // panels (K multiple of 16)

    // per-thread load assignments (2 x 16B chunks for A, 2 for W)
    const int ac0 = tid, ac1 = tid + 256;
    const int ar0 = ac0 >> 2, ak0 = (ac0 & 3) * 4;
    const int ar1 = ac1 >> 2, ak1 = (ac1 & 3) * 4;
    const int wr0 = ac0 >> 5, wn0 = (ac0 & 31) * 4;
    const int wr1 = ac1 >> 5, wn1 = (ac1 & 31) * 4;

    float acc[2][8][4];
#pragma unroll
    for (int mi = 0; mi < 2; mi++)
#pragma unroll
        for (int ni = 0; ni < 8; ni++)
#pragma unroll
            for (int r = 0; r < 4; r++) acc[mi][ni][r] = 0.0f;

    auto load_panel = [&](int p, int s) {
        int k0 = p * 16;
        uint32_t abase = (uint32_t)__cvta_generic_to_shared(&As[s][0]);
        uint32_t wbase = (uint32_t)__cvta_generic_to_shared(&Ws[s][0]);
        bool p0 = (row0 + ar0) < M;
        bool p1 = (row0 + ar1) < M;
        const float* s0 = A + (size_t)(p0 ? row0 + ar0 : 0) * SA + k0 + ak0;
        const float* s1 = A + (size_t)(p1 ? row0 + ar1 : 0) * SA + k0 + ak1;
        cp16(abase + (ar0 * ASTRIDE + ak0) * 4, s0, p0);
        cp16(abase + (ar1 * ASTRIDE + ak1) * 4, s1, p1);
        cp16(wbase + (wr0 * WSTRIDE + wn0) * 4, Wr + (size_t)(k0 + wr0) * H + wn0, true);
        cp16(wbase + (wr1 * WSTRIDE + wn1) * 4, Wr + (size_t)(k0 + wr1) * H + wn1, true);
        cp_commit();
    };

    load_panel(0, 0);

    for (int p = 0; p < P; p++) {
        int s = p & 1;
        if (p + 1 < P) {
            load_panel(p + 1, s ^ 1);
            cp_wait<1>();
        } else {
            cp_wait<0>();
        }
        __syncthreads();

        const uint32_t* as = (const uint32_t*)&As[s][0];
        const uint32_t* ws = (const uint32_t*)&Ws[s][0];
#pragma unroll
        for (int ks = 0; ks < 16; ks += 8) {
            uint32_t afr[2][4];
#pragma unroll
            for (int mi = 0; mi < 2; mi++) {
                int m0 = (wm + mi * 16 + grp) * ASTRIDE;
                int m8 = m0 + 8 * ASTRIDE;
                afr[mi][0] = as[m0 + ks + qid];
                afr[mi][1] = as[m8 + ks + qid];
                afr[mi][2] = as[m0 + ks + qid + 4];
                afr[mi][3] = as[m8 + ks + qid + 4];
            }
            uint32_t bfr[8][2];
#pragma unroll
            for (int ni = 0; ni < 8; ni++) {
                int nb = wn + ni * 8 + grp;
                bfr[ni][0] = ws[(ks + qid) * WSTRIDE + nb];
                bfr[ni][1] = ws[(ks + qid + 4) * WSTRIDE + nb];
            }
#pragma unroll
            for (int mi = 0; mi < 2; mi++)
#pragma unroll
                for (int ni = 0; ni < 8; ni++)
                    mma_tf32(acc[mi][ni], afr[mi], bfr[ni]);
        }
        __syncthreads();
    }

    // epilogue: scale by dinv, write to g_bufA
#pragma unroll
    for (int mi = 0; mi < 2; mi++) {
        int r0 = row0 + wm + mi * 16 + grp;
        int r1 = r0 + 8;
        float d0 = (r0 < M) ? g_dinv[r0] : 0.0f;
        float d1 = (r1 < M) ? g_dinv[r1] : 0.0f;
#pragma unroll
        for (int ni = 0; ni < 8; ni++) {
            int c = wn + ni * 8 + qid * 2;
            if (r0 < M) {
                float2 v = make_float2(acc[mi][ni][0] * d0, acc[mi][ni][1] * d0);
                *(float2*)(g_bufA + (size_t)r0 * H + c) = v;
            }
            if (r1 < M) {
                float2 v = make_float2(acc[mi][ni][2] * d1, acc[mi][ni][3] * d1);
                *(float2*)(g_bufA + (size_t)r1 * H + c) = v;
            }
        }
    }
}

// ---------------- aggregation: warp per node --------------------------------
// out_i = tanh(dinv_i * (hs_i + sum_{e in row i} hs[col[e]]) + b)
// Internal-layer outputs are tf32-rounded so the next GEMM's truncation is exact.
__global__ __launch_bounds__(256)
void k_aggregate(const float* __restrict__ bias, float* outext, int n) {
    const float* __restrict__ hs = g_bufA;
    float* __restrict__ out = outext ? outext : g_bufB;

    int warp = (blockIdx.x * blockDim.x + threadIdx.x) >> 5;
    if (warp >= n) return;
    int lane = threadIdx.x & 31;

    const float4* row_i = (const float4*)(hs + (size_t)warp * H);
    float4 acc = row_i[lane];                 // self term

    int e = g_rowptr[warp];
    int end = g_rowptr[warp + 1];
    for (; e + 3 < end; e += 4) {
        int j0 = g_col[e],     j1 = g_col[e + 1];
        int j2 = g_col[e + 2], j3 = g_col[e + 3];
        float4 v0 = ((const float4*)(hs + (size_t)j0 * H))[lane];
        float4 v1 = ((const float4*)(hs + (size_t)j1 * H))[lane];
        float4 v2 = ((const float4*)(hs + (size_t)j2 * H))[lane];
        float4 v3 = ((const float4*)(hs + (size_t)j3 * H))[lane];
        acc.x += v0.x; acc.y += v0.y; acc.z += v0.z; acc.w += v0.w;
        acc.x += v1.x; acc.y += v1.y; acc.z += v1.z; acc.w += v1.w;
        acc.x += v2.x; acc.y += v2.y; acc.z += v2.z; acc.w += v2.w;
        acc.x += v3.x; acc.y += v3.y; acc.z += v3.z; acc.w += v3.w;
    }
    for (; e < end; e++) {
        int j0 = g_col[e];
        float4 v0 = ((const float4*)(hs + (size_t)j0 * H))[lane];
        acc.x += v0.x; acc.y += v0.y; acc.z += v0.z; acc.w += v0.w;
    }

    float di = g_dinv[warp];
    float4 bb = ((const float4*)bias)[lane];
    float4 o;
    o.x = tanhf(di * acc.x + bb.x);
    o.y = tanhf(di * acc.y + bb.y);
    o.z = tanhf(di * acc.z + bb.z);
    o.w = tanhf(di * acc.w + bb.w);
    if (!outext) {   // feed next GEMM: pre-round to tf32 (exact MMA truncation)
        o.x = rnd_tf32(o.x); o.y = rnd_tf32(o.y);
        o.z = rnd_tf32(o.z); o.w = rnd_tf32(o.w);
    }
    ((float4*)(out + (size_t)warp * H))[lane] = o;
}

// ---------------- launch -----------------------------------------------------
extern "C" void kernel_launch(void* const* d_in, const int* in_sizes, int n_in,
                              void* d_out, int out_size) {
    const float* x  = (const float*)d_in[0];
    const int*   ei = (const int*)d_in[1];       // int32 (2, E)
    const float* W0 = (const float*)d_in[2];
    const float* b0 = (const float*)d_in[3];
    const float* W1 = (const float*)d_in[4];
    const float* b1 = (const float*)d_in[5];
    const float* W2 = (const float*)d_in[6];
    const float* b2 = (const float*)d_in[7];
    const float* W3 = (const float*)d_in[8];
    const float* b3 = (const float*)d_in[9];
    float* out = (float*)d_out;

    int N = in_sizes[0] / NF;
    int E = in_sizes[1] / 2;
    if (N > MAXN) N = MAXN;
    if (E > MAXE) E = MAXE;

    int nb = (N + 511) / 512;

    // prep (independent of graph preprocessing)
    k_prep_x<<<(N * K0P + 255) / 256, 256>>>(x, N);
    k_prep_w<<<(K0P * H + 3 * H * H + 255) / 256, 256>>>(W0, W1, W2, W3);

    // graph preprocessing
    k_zero_deg<<<(N + 255) / 256, 256>>>(N);
    k_count<<<(E + 255) / 256, 256>>>(ei, E, N);
    k_partial<<<nb, 512>>>(N);
    k_scanb<<<1, 512>>>(nb, N);
    k_rowptr<<<nb, 512>>>(N);
    k_fill<<<(E + 255) / 256, 256>>>(ei, E, N);

    int gemm_grid = (N + 127) / 128;
    int agg_grid  = (N + 7) / 8;

    // layer 0: g_xr [N,144] @ g_wr0 -> g_bufA -> g_bufB
    k_gemm_pipe<<<gemm_grid, 256>>>(0, 0, N, K0P, K0P);
    k_aggregate<<<agg_grid, 256>>>(b0, nullptr, N);
    // layer 1
    k_gemm_pipe<<<gemm_grid, 256>>>(1, 1, N, H, H);
    k_aggregate<<<agg_grid, 256>>>(b1, nullptr, N);
    // layer 2
    k_gemm_pipe<<<gemm_grid, 256>>>(1, 2, N, H, H);
    k_aggregate<<<agg_grid, 256>>>(b2, nullptr, N);
    // layer 3 -> d_out
    k_gemm_pipe<<<gemm_grid, 256>>>(1, 3, N, H, H);
    k_aggregate<<<agg_grid, 256>>>(b3, out, N);
}

// round 11
// speedup vs baseline: 3.0993x; 1.1777x over previous
#include <cuda_runtime.h>
#include <cuda_fp16.h>
#include <math.h>
#include <stdint.h>

// ---------------- problem constants ----------------------------------------
#define MAXN 100000
#define MAXE 1600000
#define H 128
#define NF 133
#define K0P 144          // layer-0 K padded to multiple of 16

// ---------------- static scratch: referenced ONLY inside device code --------
__device__ float  g_dinv[MAXN];
__device__ int    g_deg[MAXN];
__device__ int    g_rowptr[MAXN + 1];
__device__ int    g_cursor[MAXN];
__device__ int    g_col[MAXE];
__device__ __half g_hs[(size_t)MAXN * H];     // dinv-scaled GEMM output (fp16)
__device__ __half g_act[(size_t)MAXN * H];    // activations (fp16)
__device__ __half g_xh[(size_t)MAXN * K0P];   // x fp16, padded
__device__ __half g_w0T[H * K0P];             // W0^T [n][k] fp16, padded
__device__ __half g_wT[3][H * H];             // W1..3^T [n][k] fp16
__device__ int    g_bsum[512];
__device__ int    g_boff[512];

// ---------------- helpers ----------------------------------------------------
__device__ __forceinline__ void mma_f16(float c[4], const uint32_t a[4],
                                        const uint32_t b[2]) {
    asm volatile(
        "mma.sync.aligned.m16n8k16.row.col.f32.f16.f16.f32 "
        "{%0,%1,%2,%3}, {%4,%5,%6,%7}, {%8,%9}, {%0,%1,%2,%3};"
        : "+f"(c[0]), "+f"(c[1]), "+f"(c[2]), "+f"(c[3])
        : "r"(a[0]), "r"(a[1]), "r"(a[2]), "r"(a[3]), "r"(b[0]), "r"(b[1]));
}

__device__ __forceinline__ void cp16(uint32_t dst, const void* src, bool pred) {
    int sz = pred ? 16 : 0;
    asm volatile("cp.async.ca.shared.global [%0], [%1], 16, %2;"
                 :: "r"(dst), "l"(src), "r"(sz));
}
__device__ __forceinline__ void cp_commit() {
    asm volatile("cp.async.commit_group;");
}
template <int NN>
__device__ __forceinline__ void cp_wait() {
    asm volatile("cp.async.wait_group %0;" :: "n"(NN));
}

__device__ __forceinline__ float4 h4_to_f4(uint2 u) {
    __half2 a = *(__half2*)&u.x;
    __half2 b = *(__half2*)&u.y;
    float2 fa = __half22float2(a);
    float2 fb = __half22float2(b);
    return make_float4(fa.x, fa.y, fb.x, fb.y);
}

// ---------------- prep: convert inputs/weights to fp16 ----------------------
__global__ void k_prep_x(const float* __restrict__ x, int n) {
    int idx = blockIdx.x * blockDim.x + threadIdx.x;
    if (idx >= n * K0P) return;
    int row = idx / K0P, col = idx - row * K0P;
    float v = (col < NF) ? x[(size_t)row * NF + col] : 0.0f;
    g_xh[idx] = __float2half_rn(v);
}

// W stored transposed [n][k] so the B fragment packs 2 k-adjacent halves.
__global__ void k_prep_w(const float* __restrict__ W0, const float* __restrict__ W1,
                         const float* __restrict__ W2, const float* __restrict__ W3) {
    int idx = blockIdx.x * blockDim.x + threadIdx.x;
    if (idx < H * K0P) {
        int nn = idx / K0P, k = idx - nn * K0P;
        float v = (k < NF) ? W0[(size_t)k * H + nn] : 0.0f;
        g_w0T[idx] = __float2half_rn(v);
    } else if (idx < H * K0P + 3 * H * H) {
        int r = idx - H * K0P;
        int l = r / (H * H);
        int o = r - l * (H * H);
        int nn = o >> 7, k = o & 127;
        const float* W = (l == 0) ? W1 : (l == 1) ? W2 : W3;
        g_wT[l][o] = __float2half_rn(W[(size_t)k * H + nn]);
    }
}

// ---------------- preprocessing kernels -------------------------------------
__global__ void k_zero_deg(int n) {
    int i = blockIdx.x * blockDim.x + threadIdx.x;
    if (i < n) g_deg[i] = 0;
}

// vectorized: 4 edges per thread via int4
__global__ void k_count(const int* __restrict__ ei, int E, int n) {
    int t = blockIdx.x * blockDim.x + threadIdx.x;
    int E4 = E >> 2;
    if (((E & 3) == 0)) {
        if (t < E4) {
            int4 d = ((const int4*)(ei + E))[t];
            if ((unsigned)d.x < (unsigned)n) atomicAdd(&g_deg[d.x], 1);
            if ((unsigned)d.y < (unsigned)n) atomicAdd(&g_deg[d.y], 1);
            if ((unsigned)d.z < (unsigned)n) atomicAdd(&g_deg[d.z], 1);
            if ((unsigned)d.w < (unsigned)n) atomicAdd(&g_deg[d.w], 1);
        }
    } else {
        int e = t;
        if (e < E) {
            int d = ei[E + e];
            if ((unsigned)d < (unsigned)n) atomicAdd(&g_deg[d], 1);
        }
    }
}

__global__ void k_partial(int n) {
    __shared__ int s[512];
    int t = threadIdx.x;
    int i = blockIdx.x * 512 + t;
    s[t] = (i < n) ? g_deg[i] : 0;
    __syncthreads();
    for (int off = 256; off > 0; off >>= 1) {
        if (t < off) s[t] += s[t + off];
        __syncthreads();
    }
    if (t == 0) g_bsum[blockIdx.x] = s[0];
}

__global__ void k_scanb(int nb, int n) {
    __shared__ int s[512];
    int t = threadIdx.x;
    int v = (t < nb) ? g_bsum[t] : 0;
    s[t] = v;
    __syncthreads();
    for (int off = 1; off < 512; off <<= 1) {
        int x = (t >= off) ? s[t - off] : 0;
        __syncthreads();
        s[t] += x;
        __syncthreads();
    }
    if (t < nb) g_boff[t] = s[t] - v;
    if (t == 511) g_rowptr[n] = s[511];
}

__global__ void k_rowptr(int n) {
    __shared__ int s[512];
    int t = threadIdx.x;
    int i = blockIdx.x * 512 + t;
    int v = (i < n) ? g_deg[i] : 0;
    s[t] = v;
    __syncthreads();
    for (int off = 1; off < 512; off <<= 1) {
        int x = (t >= off) ? s[t - off] : 0;
        __syncthreads();
        s[t] += x;
        __syncthreads();
    }
    if (i < n) {
        int rp = g_boff[blockIdx.x] + s[t] - v;
        g_rowptr[i] = rp;
        g_cursor[i] = rp;
        g_dinv[i] = rsqrtf((float)v + 1.0f);
    }
}

// vectorized fill: 4 edges per thread
__global__ void k_fill(const int* __restrict__ ei, int E, int n) {
    int t = blockIdx.x * blockDim.x + threadIdx.x;
    int E4 = E >> 2;
    if (((E & 3) == 0)) {
        if (t < E4) {
            int4 sv = ((const int4*)ei)[t];
            int4 dv = ((const int4*)(ei + E))[t];
            if ((unsigned)dv.x < (unsigned)n && (unsigned)sv.x < (unsigned)n) {
                int pos = atomicAdd(&g_cursor[dv.x], 1);
                if ((unsigned)pos < (unsigned)E) g_col[pos] = sv.x;
            }
            if ((unsigned)dv.y < (unsigned)n && (unsigned)sv.y < (unsigned)n) {
                int pos = atomicAdd(&g_cursor[dv.y], 1);
                if ((unsigned)pos < (unsigned)E) g_col[pos] = sv.y;
            }
            if ((unsigned)dv.z < (unsigned)n && (unsigned)sv.z < (unsigned)n) {
                int pos = atomicAdd(&g_cursor[dv.z], 1);
                if ((unsigned)pos < (unsigned)E) g_col[pos] = sv.z;
            }
            if ((unsigned)dv.w < (unsigned)n && (unsigned)sv.w < (unsigned)n) {
                int pos = atomicAdd(&g_cursor[dv.w], 1);
                if ((unsigned)pos < (unsigned)E) g_col[pos] = sv.w;
            }
        }
    } else {
        int e = t;
        if (e < E) {
            int srcv = ei[e];
            int d    = ei[E + e];
            if ((unsigned)d < (unsigned)n && (unsigned)srcv < (unsigned)n) {
                int pos = atomicAdd(&g_cursor[d], 1);
                if ((unsigned)pos < (unsigned)E) g_col[pos] = srcv;
            }
        }
    }
}

// ---------------- GEMM (fp16 TC, cp.async double-buffered) -------------------
// g_hs = fp16( (A[M,K] @ W[K,128]) * dinv[row] ).
// asel: 0 -> A = g_xh (stride K0P), 1 -> A = g_act (stride H).
// wsel: 0..3 selects W^T array. All symbols resolved in device code.
// CTA 128x128, BK=16 (one k16 MMA step/panel), 8 warps x (32x64).
__global__ __launch_bounds__(256, 2)
void k_gemm_f16(int asel, int wsel, int M, int K, int SA) {
    const __half* __restrict__ A  = (asel == 0) ? g_xh : g_act;
    const __half* __restrict__ WT = (wsel == 0) ? g_w0T : g_wT[wsel - 1];
    // smem tiles: A [128 rows][16 halves] = 8 words/row; W^T same shape
    __shared__ uint32_t As[2][128 * 8];
    __shared__ uint32_t Ws[2][128 * 8];

    const int tid  = threadIdx.x;
    const int lane = tid & 31;
    const int w    = tid >> 5;
    const int wm   = (w >> 1) * 32;
    const int wn   = (w & 1) * 64;
    const int grp  = lane >> 2;
    const int qid  = lane & 3;
    const int row0 = blockIdx.x * 128;
    const int P    = K >> 4;

    // loaders: 256 chunks of 16B per tile, 1 chunk each per thread
    const int lrow = tid >> 1;            // 0..127
    const int lh   = (tid & 1) * 8;       // half offset within row
    const int lw   = (tid & 1) * 4;       // word offset

    float acc[2][8][4];
#pragma unroll
    for (int mi = 0; mi < 2; mi++)
#pragma unroll
        for (int ni = 0; ni < 8; ni++)
#pragma unroll
            for (int r = 0; r < 4; r++) acc[mi][ni][r] = 0.0f;

    auto load_panel = [&](int p, int s) {
        int k0 = p * 16;
        uint32_t ab = (uint32_t)__cvta_generic_to_shared(&As[s][0]);
        uint32_t wb = (uint32_t)__cvta_generic_to_shared(&Ws[s][0]);
        bool pa = (row0 + lrow) < M;
        const __half* sa = A + (size_t)(pa ? row0 + lrow : 0) * SA + k0 + lh;
        cp16(ab + (lrow * 8 + lw) * 4, sa, pa);
        const __half* sw = WT + (size_t)lrow * K + k0 + lh;
        cp16(wb + (lrow * 8 + lw) * 4, sw, true);
        cp_commit();
    };

    load_panel(0, 0);

    for (int p = 0; p < P; p++) {
        int s = p & 1;
        if (p + 1 < P) {
            load_panel(p + 1, s ^ 1);
            cp_wait<1>();
        } else {
            cp_wait<0>();
        }
        __syncthreads();

        const uint32_t* as = &As[s][0];
        const uint32_t* ws = &Ws[s][0];
        uint32_t afr[2][4];
#pragma unroll
        for (int mi = 0; mi < 2; mi++) {
            int r = wm + mi * 16 + grp;
            afr[mi][0] = as[r * 8 + qid];
            afr[mi][1] = as[(r + 8) * 8 + qid];
            afr[mi][2] = as[r * 8 + qid + 4];
            afr[mi][3] = as[(r + 8) * 8 + qid + 4];
        }
        uint32_t bfr[8][2];
#pragma unroll
        for (int ni = 0; ni < 8; ni++) {
            int nn = wn + ni * 8 + grp;
            bfr[ni][0] = ws[nn * 8 + qid];
            bfr[ni][1] = ws[nn * 8 + qid + 4];
        }
#pragma unroll
        for (int mi = 0; mi < 2; mi++)
#pragma unroll
            for (int ni = 0; ni < 8; ni++)
                mma_f16(acc[mi][ni], afr[mi], bfr[ni]);
        __syncthreads();
    }

    // epilogue: scale by dinv, store fp16 to g_hs
#pragma unroll
    for (int mi = 0; mi < 2; mi++) {
        int r0 = row0 + wm + mi * 16 + grp;
        int r1 = r0 + 8;
        float d0 = (r0 < M) ? g_dinv[r0] : 0.0f;
        float d1 = (r1 < M) ? g_dinv[r1] : 0.0f;
#pragma unroll
        for (int ni = 0; ni < 8; ni++) {
            int c = wn + ni * 8 + qid * 2;
            if (r0 < M) {
                __half2 hv = __floats2half2_rn(acc[mi][ni][0] * d0, acc[mi][ni][1] * d0);
                *(__half2*)(g_hs + (size_t)r0 * H + c) = hv;
            }
            if (r1 < M) {
                __half2 hv = __floats2half2_rn(acc[mi][ni][2] * d1, acc[mi][ni][3] * d1);
                *(__half2*)(g_hs + (size_t)r1 * H + c) = hv;
            }
        }
    }
}

// ---------------- aggregation: warp per node (fp16 gather, fp32 accum) -------
// out_i = tanh(dinv_i * (hs_i + sum_{e in row i} hs[col[e]]) + b)
__global__ __launch_bounds__(256)
void k_aggregate(const float* __restrict__ bias, float* outext, int n) {
    int warp = (blockIdx.x * blockDim.x + threadIdx.x) >> 5;
    if (warp >= n) return;
    int lane = threadIdx.x & 31;

    const uint2* __restrict__ hp = (const uint2*)g_hs;  // 32 uint2 per row

    uint2 sv = hp[(size_t)warp * 32 + lane];
    float4 acc = h4_to_f4(sv);                 // self term

    int e = g_rowptr[warp];
    int end = g_rowptr[warp + 1];
    for (; e + 3 < end; e += 4) {
        int j0 = g_col[e],     j1 = g_col[e + 1];
        int j2 = g_col[e + 2], j3 = g_col[e + 3];
        float4 v0 = h4_to_f4(hp[(size_t)j0 * 32 + lane]);
        float4 v1 = h4_to_f4(hp[(size_t)j1 * 32 + lane]);
        float4 v2 = h4_to_f4(hp[(size_t)j2 * 32 + lane]);
        float4 v3 = h4_to_f4(hp[(size_t)j3 * 32 + lane]);
        acc.x += v0.x; acc.y += v0.y; acc.z += v0.z; acc.w += v0.w;
        acc.x += v1.x; acc.y += v1.y; acc.z += v1.z; acc.w += v1.w;
        acc.x += v2.x; acc.y += v2.y; acc.z += v2.z; acc.w += v2.w;
        acc.x += v3.x; acc.y += v3.y; acc.z += v3.z; acc.w += v3.w;
    }
    for (; e < end; e++) {
        float4 v0 = h4_to_f4(hp[(size_t)g_col[e] * 32 + lane]);
        acc.x += v0.x; acc.y += v0.y; acc.z += v0.z; acc.w += v0.w;
    }

    float di = g_dinv[warp];
    float4 bb = ((const float4*)bias)[lane];
    float4 o;
    o.x = tanhf(di * acc.x + bb.x);
    o.y = tanhf(di * acc.y + bb.y);
    o.z = tanhf(di * acc.z + bb.z);
    o.w = tanhf(di * acc.w + bb.w);

    if (outext) {
        ((float4*)outext)[(size_t)warp * 32 + lane] = o;   // final layer: fp32
    } else {
        __half2 lo = __floats2half2_rn(o.x, o.y);
        __half2 hi = __floats2half2_rn(o.z, o.w);
        uint2 u;
        u.x = *(uint32_t*)&lo;
        u.y = *(uint32_t*)&hi;
        ((uint2*)g_act)[(size_t)warp * 32 + lane] = u;     // next GEMM input
    }
}

// ---------------- launch -----------------------------------------------------
extern "C" void kernel_launch(void* const* d_in, const int* in_sizes, int n_in,
                              void* d_out, int out_size) {
    const float* x  = (const float*)d_in[0];
    const int*   ei = (const int*)d_in[1];       // int32 (2, E)
    const float* W0 = (const float*)d_in[2];
    const float* b0 = (const float*)d_in[3];
    const float* W1 = (const float*)d_in[4];
    const float* b1 = (const float*)d_in[5];
    const float* W2 = (const float*)d_in[6];
    const float* b2 = (const float*)d_in[7];
    const float* W3 = (const float*)d_in[8];
    const float* b3 = (const float*)d_in[9];
    float* out = (float*)d_out;

    int N = in_sizes[0] / NF;
    int E = in_sizes[1] / 2;
    if (N > MAXN) N = MAXN;
    if (E > MAXE) E = MAXE;

    int nb = (N + 511) / 512;
    int ecnt = ((E & 3) == 0) ? (E >> 2) : E;    // threads for count/fill

    // prep
    k_prep_x<<<(N * K0P + 255) / 256, 256>>>(x, N);
    k_prep_w<<<(H * K0P + 3 * H * H + 255) / 256, 256>>>(W0, W1, W2, W3);

    // graph preprocessing
    k_zero_deg<<<(N + 255) / 256, 256>>>(N);
    k_count<<<(ecnt + 255) / 256, 256>>>(ei, E, N);
    k_partial<<<nb, 512>>>(N);
    k_scanb<<<1, 512>>>(nb, N);
    k_rowptr<<<nb, 512>>>(N);
    k_fill<<<(ecnt + 255) / 256, 256>>>(ei, E, N);

    int gemm_grid = (N + 127) / 128;
    int agg_grid  = (N + 7) / 8;

    // layer 0: g_xh [N,144] @ W0 -> g_hs -> g_act
    k_gemm_f16<<<gemm_grid, 256>>>(0, 0, N, K0P, K0P);
    k_aggregate<<<agg_grid, 256>>>(b0, nullptr, N);
    // layer 1
    k_gemm_f16<<<gemm_grid, 256>>>(1, 1, N, H, H);
    k_aggregate<<<agg_grid, 256>>>(b1, nullptr, N);
    // layer 2
    k_gemm_f16<<<gemm_grid, 256>>>(1, 2, N, H, H);
    k_aggregate<<<agg_grid, 256>>>(b2, nullptr, N);
    // layer 3 -> d_out (fp32)
    k_gemm_f16<<<gemm_grid, 256>>>(1, 3, N, H, H);
    k_aggregate<<<agg_grid, 256>>>(b3, out, N);
}